// round 13
// baseline (speedup 1.0000x reference)
#include <cuda_runtime.h>
#include <cuda_fp16.h>
#include <math.h>
#include <stdint.h>

#define BN 8192
#define DK 256
#define NT 64                            // 128-row tiles
#define NBLK 1056                        // 1024 pair-blocks + 32 odd-diag singles
#define TEMP_INV 14.2857142857142857f    // 1/0.07

// ---------------- static device scratch ----------------
__device__ __align__(16) __half g_znh[BN * DK];   // fp16 normalized z_flowed (4 MB)
__device__ unsigned char g_ao[BN];                // allones flag per row
__device__ __align__(16) float g_pall[BN * NT];   // partial all-sums [row][tile]
__device__ __align__(16) float g_ppos[BN * NT];   // partial pos-sums [row][tile]
__device__ float g_blocksum[32];
__device__ unsigned int g_blockcnt[32];
__device__ unsigned int g_ticket;

__device__ __forceinline__ uint32_t smem_u32(const void* p) {
    uint32_t a;
    asm("{ .reg .u64 t; cvta.to.shared.u64 t, %1; cvt.u32.u64 %0, t; }" : "=r"(a) : "l"(p));
    return a;
}
__device__ __forceinline__ void ldsm_x4(uint32_t& r0, uint32_t& r1, uint32_t& r2, uint32_t& r3,
                                        uint32_t addr) {
    asm volatile("ldmatrix.sync.aligned.m8n8.x4.shared.b16 {%0,%1,%2,%3}, [%4];"
                 : "=r"(r0), "=r"(r1), "=r"(r2), "=r"(r3) : "r"(addr));
}
__device__ __forceinline__ void mma16816_f16(uint32_t* d, const uint32_t* a,
                                             uint32_t b0, uint32_t b1) {
    asm volatile(
        "mma.sync.aligned.m16n8k16.row.col.f16.f16.f16.f16 "
        "{%0,%1}, {%2,%3,%4,%5}, {%6,%7}, {%0,%1};"
        : "+r"(d[0]), "+r"(d[1])
        : "r"(a[0]), "r"(a[1]), "r"(a[2]), "r"(a[3]), "r"(b0), "r"(b1));
}
__device__ __forceinline__ void cp16(uint32_t dst, const void* src) {
    asm volatile("cp.async.cg.shared.global [%0], [%1], 16;" :: "r"(dst), "l"(src) : "memory");
}
#define CP_COMMIT() asm volatile("cp.async.commit_group;" ::: "memory")
#define CP_WAIT(n)  asm volatile("cp.async.wait_group %0;" :: "n"(n) : "memory")

// smem layout (dynamic)
#define OFF_AOI   0        // 128 B
#define OFF_AOJ   128      // 256 B
#define OFF_RPA   384      // [4][128] f32
#define OFF_RPP   2432
#define OFF_CPA   4480     // [2][256] f32
#define OFF_CPP   6528
#define OFF_A0    9216     // A chunk: 128 rows x 128 B = 16 KB
#define OFF_B0    25600    // B chunk: 256 rows x 128 B = 32 KB
#define OFF_A1    58368
#define OFF_B1    74752
#define SMEM_TOTAL 107520

// ---------------- kernel 1: warp-per-row L2-normalize (fp16 out) + allones ----------------
__global__ void k_norm(const float* __restrict__ zf, const float* __restrict__ attr) {
    const int row = blockIdx.x * 8 + (threadIdx.x >> 5);
    const int lane = threadIdx.x & 31;
    const float4* src = reinterpret_cast<const float4*>(zf + row * DK);
    float4 v0 = src[lane * 2];
    float4 v1 = src[lane * 2 + 1];
    float ss = v0.x * v0.x + v0.y * v0.y + v0.z * v0.z + v0.w * v0.w
             + v1.x * v1.x + v1.y * v1.y + v1.z * v1.z + v1.w * v1.w;
    #pragma unroll
    for (int o = 16; o; o >>= 1) ss += __shfl_xor_sync(0xffffffffu, ss, o);
    float inv = 1.0f / fmaxf(sqrtf(ss), 1e-12f);

    __half2 h[4];
    h[0] = __floats2half2_rn(v0.x * inv, v0.y * inv);
    h[1] = __floats2half2_rn(v0.z * inv, v0.w * inv);
    h[2] = __floats2half2_rn(v1.x * inv, v1.y * inv);
    h[3] = __floats2half2_rn(v1.z * inv, v1.w * inv);
    *reinterpret_cast<uint4*>(&g_znh[row * DK + lane * 8]) = *reinterpret_cast<uint4*>(h);

    if (lane == 0) {
        const float* a = attr + row * 4;
        g_ao[row] = ((a[0] + a[1] + a[2] + a[3]) == 4.0f) ? 1 : 0;
    }
}

// ---- chunk loader: K-chunk (64 halves) of A (128 rows) and B (256 col-rows) ----
__device__ __forceinline__ void load_chunk(uint32_t sbase, uint32_t offA, uint32_t offB,
                                           int i0, int j0, bool dup, int kc, int tid) {
    #pragma unroll
    for (int u = 0; u < 4; u++) {
        int idx = tid + 256 * u;          // 0..1023
        int r = idx >> 3;
        int c = idx & 7;
        int phys = (c ^ r) & 7;
        cp16(sbase + offA + r * 128 + phys * 16, &g_znh[(i0 + r) * DK + kc * 64 + c * 8]);
    }
    #pragma unroll
    for (int u = 0; u < 8; u++) {
        int idx = tid + 256 * u;          // 0..2047
        int r = idx >> 3;                 // 0..255
        int c = idx & 7;
        int phys = (c ^ r) & 7;
        int gr = j0 + (dup ? (r & 127) : r);
        cp16(sbase + offB + r * 128 + phys * 16, &g_znh[gr * DK + kc * 64 + c * 8]);
    }
    CP_COMMIT();
}

// ---- chunk compute: 4 k-steps over one buffered chunk; warp tile 64x64 ----
__device__ __forceinline__ void compute_chunk(uint32_t sbase, uint32_t offA, uint32_t offB,
                                              int wr, int wc, int lane,
                                              uint32_t (&acc)[4][8][2]) {
    #pragma unroll
    for (int kk = 0; kk < 4; kk++) {
        uint32_t afr[4][4], bfr[4][4];
        const int cch = kk * 2 + (lane >> 4);
        #pragma unroll
        for (int mi = 0; mi < 4; mi++) {
            int r = wr * 64 + mi * 16 + (lane & 15);
            int phys = (cch ^ r) & 7;
            ldsm_x4(afr[mi][0], afr[mi][1], afr[mi][2], afr[mi][3],
                    sbase + offA + r * 128 + phys * 16);
        }
        #pragma unroll
        for (int n2 = 0; n2 < 4; n2++) {
            int r = wc * 64 + n2 * 16 + (lane & 15);
            int phys = (cch ^ r) & 7;
            ldsm_x4(bfr[n2][0], bfr[n2][1], bfr[n2][2], bfr[n2][3],
                    sbase + offB + r * 128 + phys * 16);
        }
        #pragma unroll
        for (int mi = 0; mi < 4; mi++)
            #pragma unroll
            for (int ni = 0; ni < 8; ni++) {
                int n2 = ni >> 1, odd = ni & 1;
                mma16816_f16(acc[mi][ni], afr[mi], bfr[n2][odd], bfr[n2][odd + 2]);
            }
    }
}

// ---------------- kernel 2: HMMA gram, 128x256 block tile ----------------
__global__ __launch_bounds__(256) void k_gram_mma() {
    extern __shared__ char smem[];
    const int b = blockIdx.x;
    int it, jt0;
    bool dup;
    if (b < 1024) {
        int J = (int)sqrtf((float)b);
        while ((J + 1) * (J + 1) <= b) J++;
        while (J * J > b) J--;
        it = b - J * J;                  // 0..2J
        jt0 = 2 * J;
        dup = false;
    } else {
        it = 2 * (b - 1024) + 1;         // odd diagonal singles
        jt0 = it;
        dup = true;
    }
    const bool diag0 = (it == jt0);
    const int i0 = it * 128, j0 = jt0 * 128;

    const uint32_t sbase = smem_u32(smem);
    const int tid = threadIdx.x;
    const int wid = tid >> 5;
    const int lane = tid & 31;
    const int wr = wid & 1;               // 0..1 -> 64 rows
    const int wc = wid >> 1;              // 0..3 -> 64 cols

    if (tid < 128) smem[OFF_AOI + tid] = (char)g_ao[i0 + tid];
    smem[OFF_AOJ + tid] = (char)g_ao[j0 + (dup ? (tid & 127) : tid)];

    uint32_t acc[4][8][2];
    #pragma unroll
    for (int mi = 0; mi < 4; mi++)
        #pragma unroll
        for (int ni = 0; ni < 8; ni++) { acc[mi][ni][0] = 0u; acc[mi][ni][1] = 0u; }

    load_chunk(sbase, OFF_A0, OFF_B0, i0, j0, dup, 0, tid);
    load_chunk(sbase, OFF_A1, OFF_B1, i0, j0, dup, 1, tid);

    CP_WAIT(1); __syncthreads();
    compute_chunk(sbase, OFF_A0, OFF_B0, wr, wc, lane, acc);
    __syncthreads();
    load_chunk(sbase, OFF_A0, OFF_B0, i0, j0, dup, 2, tid);

    CP_WAIT(1); __syncthreads();
    compute_chunk(sbase, OFF_A1, OFF_B1, wr, wc, lane, acc);
    __syncthreads();
    load_chunk(sbase, OFF_A1, OFF_B1, i0, j0, dup, 3, tid);

    CP_WAIT(1); __syncthreads();
    compute_chunk(sbase, OFF_A0, OFF_B0, wr, wc, lane, acc);

    CP_WAIT(0); __syncthreads();
    compute_chunk(sbase, OFF_A1, OFF_B1, wr, wc, lane, acc);

    // ---- epilogue: exp + dual masked sums ----
    const int g = lane >> 2;
    const int cp2 = (lane & 3) * 2;
    float rs[8], rp[8], cs[16], cpn[16];
    #pragma unroll
    for (int x = 0; x < 8; x++) { rs[x] = rp[x] = 0.f; }
    #pragma unroll
    for (int x = 0; x < 16; x++) { cs[x] = cpn[x] = 0.f; }

    #pragma unroll
    for (int mi = 0; mi < 4; mi++) {
        #pragma unroll
        for (int h = 0; h < 2; h++) {
            int rloc = wr * 64 + mi * 16 + h * 8 + g;
            bool aoi_r = smem[OFF_AOI + rloc] != 0;
            #pragma unroll
            for (int ni = 0; ni < 8; ni++) {
                float2 v = __half22float2(*reinterpret_cast<__half2*>(&acc[mi][ni][h]));
                #pragma unroll
                for (int q = 0; q < 2; q++) {
                    int cloc = wc * 64 + ni * 8 + cp2 + q;
                    float e = __expf((q ? v.y : v.x) * TEMP_INV);
                    if (dup && cloc >= 128) e = 0.f;           // duplicated half: no work
                    if (diag0 && rloc == cloc) e = 0.f;        // zero diagonal
                    rs[mi * 2 + h] += e;
                    if (smem[OFF_AOJ + cloc]) rp[mi * 2 + h] += e;
                    cs[ni * 2 + q] += e;
                    if (aoi_r) cpn[ni * 2 + q] += e;
                }
            }
        }
    }

    #pragma unroll
    for (int x = 0; x < 8; x++) {
        rs[x] += __shfl_xor_sync(0xffffffffu, rs[x], 1);
        rs[x] += __shfl_xor_sync(0xffffffffu, rs[x], 2);
        rp[x] += __shfl_xor_sync(0xffffffffu, rp[x], 1);
        rp[x] += __shfl_xor_sync(0xffffffffu, rp[x], 2);
    }
    float* rpa = reinterpret_cast<float*>(smem + OFF_RPA);
    float* rpp = reinterpret_cast<float*>(smem + OFF_RPP);
    if ((lane & 3) == 0) {
        #pragma unroll
        for (int mi = 0; mi < 4; mi++)
            #pragma unroll
            for (int h = 0; h < 2; h++) {
                int rloc = wr * 64 + mi * 16 + h * 8 + g;
                rpa[wc * 128 + rloc] = rs[mi * 2 + h];
                rpp[wc * 128 + rloc] = rp[mi * 2 + h];
            }
    }

    #pragma unroll
    for (int x = 0; x < 16; x++) {
        cs[x]  += __shfl_xor_sync(0xffffffffu, cs[x], 4);
        cs[x]  += __shfl_xor_sync(0xffffffffu, cs[x], 8);
        cs[x]  += __shfl_xor_sync(0xffffffffu, cs[x], 16);
        cpn[x] += __shfl_xor_sync(0xffffffffu, cpn[x], 4);
        cpn[x] += __shfl_xor_sync(0xffffffffu, cpn[x], 8);
        cpn[x] += __shfl_xor_sync(0xffffffffu, cpn[x], 16);
    }
    float* cpa = reinterpret_cast<float*>(smem + OFF_CPA);
    float* cpp = reinterpret_cast<float*>(smem + OFF_CPP);
    if (lane < 4) {
        #pragma unroll
        for (int ni = 0; ni < 8; ni++)
            #pragma unroll
            for (int q = 0; q < 2; q++) {
                int cloc = wc * 64 + ni * 8 + lane * 2 + q;
                cpa[wr * 256 + cloc] = cs[ni * 2 + q];
                cpp[wr * 256 + cloc] = cpn[ni * 2 + q];
            }
    }
    __syncthreads();

    // row sums -> slot [i][jt0] (combined over both col tiles); zero slot [i][jt0+1]
    if (tid < 128) {
        float a = rpa[tid] + rpa[128 + tid] + rpa[256 + tid] + rpa[384 + tid];
        float p = rpp[tid] + rpp[128 + tid] + rpp[256 + tid] + rpp[384 + tid];
        int row = i0 + tid;
        g_pall[row * NT + jt0] = a;
        g_ppos[row * NT + jt0] = (smem[OFF_AOI + tid] != 0) ? p : 0.f;
        if (!dup) {
            g_pall[row * NT + jt0 + 1] = 0.f;
            g_ppos[row * NT + jt0 + 1] = 0.f;
        }
    }
    // col sums -> slot [j][it]; skip dup blocks and the diagonal sub-tile
    if (!dup && !(diag0 && tid < 128)) {
        float a = cpa[tid] + cpa[256 + tid];
        float p = cpp[tid] + cpp[256 + tid];
        int jg = j0 + tid;
        g_pall[jg * NT + it] = a;
        g_ppos[jg * NT + it] = (smem[OFF_AOJ + tid] != 0) ? p : 0.f;
    }
}

// ---------------- kernel 3: per-row loss + last-block final reduction ----------------
__global__ void k_rowloss_final(float* __restrict__ out) {
    int i = blockIdx.x * blockDim.x + threadIdx.x;
    const float4* pa = reinterpret_cast<const float4*>(&g_pall[i * NT]);
    const float4* pp = reinterpret_cast<const float4*>(&g_ppos[i * NT]);
    float all = 0.f, pos = 0.f;
    #pragma unroll
    for (int t = 0; t < NT / 4; t++) {
        float4 a = pa[t], p = pp[t];
        all += a.x + a.y + a.z + a.w;
        pos += p.x + p.y + p.z + p.w;
    }
    bool valid = (g_ao[i] != 0) && (pos > 0.f);
    float loss = valid ? (logf(all) - logf(pos)) : 0.f;
    unsigned int cnt = valid ? 1u : 0u;
    #pragma unroll
    for (int o = 16; o; o >>= 1) {
        loss += __shfl_xor_sync(0xffffffffu, loss, o);
        cnt  += __shfl_xor_sync(0xffffffffu, cnt, o);
    }
    __shared__ float ws[8];
    __shared__ unsigned int wcv[8];
    __shared__ bool s_last;
    int tid = threadIdx.x;
    if ((tid & 31) == 0) { ws[tid >> 5] = loss; wcv[tid >> 5] = cnt; }
    __syncthreads();
    if (tid == 0) {
        float s = 0.f; unsigned int c = 0u;
        #pragma unroll
        for (int k = 0; k < 8; k++) { s += ws[k]; c += wcv[k]; }
        g_blocksum[blockIdx.x] = s;
        g_blockcnt[blockIdx.x] = c;
        __threadfence();
        unsigned int t = atomicAdd(&g_ticket, 1u);
        s_last = (t == gridDim.x - 1);
    }
    __syncthreads();
    if (s_last && tid < 32) {
        float s = g_blocksum[tid];
        unsigned int c = g_blockcnt[tid];
        #pragma unroll
        for (int o = 16; o; o >>= 1) {
            s += __shfl_xor_sync(0xffffffffu, s, o);
            c += __shfl_xor_sync(0xffffffffu, c, o);
        }
        if (tid == 0) {
            out[0] = (c > 0u) ? (s / (float)c) : 0.f;
            g_ticket = 0;   // reset for next graph replay
        }
    }
}

// ---------------- entry point ----------------
extern "C" void kernel_launch(void* const* d_in, const int* in_sizes, int n_in,
                              void* d_out, int out_size) {
    const float* zf   = (const float*)d_in[1];
    const float* attr = (const float*)d_in[2];
    float* out = (float*)d_out;

    cudaFuncSetAttribute(k_gram_mma, cudaFuncAttributeMaxDynamicSharedMemorySize, SMEM_TOTAL);

    k_norm<<<BN / 8, 256>>>(zf, attr);
    k_gram_mma<<<NBLK, 256, SMEM_TOTAL>>>();
    k_rowloss_final<<<BN / 256, 256>>>(out);
}